// round 13
// baseline (speedup 1.0000x reference)
#include <cuda_runtime.h>
#include <math.h>

// Problem constants (fixed shapes per reference)
#define T_SEQ 16384
#define DDIM  1024

// ---------------- scratch (static device allocations) ----------------------------
__device__ float    g_xwx[T_SEQ * DDIM];   // X@Wx + bh, 64 MB
// Per-CTA monotonic progress flags, padded to one 32B sector each.
// g_flag[b*8] = number of steps CTA b has completed (t+1). Memset 0 per launch.
__device__ unsigned g_flag[64 * 8];

// ---------------- fp32 SGEMM: C[M,N] = A[M,K] @ B[K,N] + bias[N] ----------------
__global__ __launch_bounds__(256, 2)
void sgemm_bias_kernel(const float* __restrict__ A, const float* __restrict__ B,
                       const float* __restrict__ bias, float* __restrict__ C,
                       int M, int N, int K) {
    __shared__ float As[8][128];
    __shared__ float Bs[8][128];

    const int bx = blockIdx.x;
    const int by = blockIdx.y;
    const int tid = threadIdx.x;

    const int rowA = tid >> 1;
    const int colA = (tid & 1) * 4;
    const int rowB = tid >> 5;
    const int colB = (tid & 31) * 4;

    const int tr = tid / 16;
    const int tc = tid % 16;

    float accum[8][8];
#pragma unroll
    for (int i = 0; i < 8; i++)
#pragma unroll
        for (int j = 0; j < 8; j++) accum[i][j] = 0.0f;

    const float* Aptr = A + (size_t)(by * 128) * K;
    const float* Bptr = B + bx * 128;

    for (int k0 = 0; k0 < K; k0 += 8) {
        float4 a4 = *(const float4*)(Aptr + (size_t)rowA * K + k0 + colA);
        As[colA + 0][rowA] = a4.x;
        As[colA + 1][rowA] = a4.y;
        As[colA + 2][rowA] = a4.z;
        As[colA + 3][rowA] = a4.w;
        float4 b4 = *(const float4*)(Bptr + (size_t)(k0 + rowB) * N + colB);
        *(float4*)&Bs[rowB][colB] = b4;
        __syncthreads();

#pragma unroll
        for (int k = 0; k < 8; k++) {
            float ra[8], rb[8];
            *(float4*)&ra[0] = *(const float4*)&As[k][tr * 8];
            *(float4*)&ra[4] = *(const float4*)&As[k][tr * 8 + 4];
            *(float4*)&rb[0] = *(const float4*)&Bs[k][tc * 8];
            *(float4*)&rb[4] = *(const float4*)&Bs[k][tc * 8 + 4];
#pragma unroll
            for (int i = 0; i < 8; i++)
#pragma unroll
                for (int j = 0; j < 8; j++)
                    accum[i][j] += ra[i] * rb[j];
        }
        __syncthreads();
    }

    const int cRow = by * 128 + tr * 8;
    const int cCol = bx * 128 + tc * 8;
    float bv[8];
#pragma unroll
    for (int j = 0; j < 8; j++) bv[j] = bias[cCol + j];

#pragma unroll
    for (int i = 0; i < 8; i++) {
        float4 v0, v1;
        v0.x = accum[i][0] + bv[0];
        v0.y = accum[i][1] + bv[1];
        v0.z = accum[i][2] + bv[2];
        v0.w = accum[i][3] + bv[3];
        v1.x = accum[i][4] + bv[4];
        v1.y = accum[i][5] + bv[5];
        v1.z = accum[i][6] + bv[6];
        v1.w = accum[i][7] + bv[7];
        *(float4*)&C[(size_t)(cRow + i) * N + cCol]     = v0;
        *(float4*)&C[(size_t)(cRow + i) * N + cCol + 4] = v1;
    }
}

// ---------------- persistent recurrence kernel (segmented, flag sync) -----------
// 64 CTAs x 128 threads (4 warps). CTA b owns h-columns [16b, 16b+16).
// Warp w owns 4 output columns cb = 16b + 4w .. +3 (Wh cols in registers).
//
// Per step:
//  PRODUCE: lane0 of each warp STG.128s its 4 tanh outputs; warps fan-in via
//    smem atom.acq_rel; the LAST warp does ONE st.release.gpu of this CTA's
//    padded flag (value t+1). 64 parallel flag stores chip-wide -- NO
//    same-address atomic train (B300: 64 serialized reds = ~1750 cyc/step).
//  CONSUME: warp0 polls all 64 flags (2 ld.acquire.gpu per lane, spread
//    sectors; R4-proven), then relays via a cta-scope release/acquire smem
//    word; warps 1-3 spin on it (no __syncthreads, warps stay autonomous).
//    All warps then __ldcg the h row directly (correct after acquire chain).
#define GBLK 64
#define WPB  4

__device__ __forceinline__ float fast_tanh(float x) {
    // tanh(x) = 1 - 2/(e^{2x}+1); MUFU-based, ~1e-7 rel err (tolerance 1e-3).
    float e = __expf(2.0f * x);
    return 1.0f - __fdividef(2.0f, e + 1.0f);
}

__global__ __launch_bounds__(128, 1)
void rnn_recurrence_kernel(const float* __restrict__ Wh, float* __restrict__ hidden,
                           int t_begin, int t_end) {
    __shared__ unsigned s_arrive;
    __shared__ unsigned s_ready;    // cta-scope release/acquire relay word

    const int tid  = threadIdx.x;
    const int lane = tid & 31;
    const int warp = tid >> 5;                      // 0..3
    const int cb   = blockIdx.x * 16 + warp * 4;    // 4 owned output columns

    if (tid == 0) { s_arrive = 0u; s_ready = 0u; }
    __syncthreads();
    const unsigned s_arrive_addr = (unsigned)__cvta_generic_to_shared(&s_arrive);
    const unsigned s_ready_addr  = (unsigned)__cvta_generic_to_shared(&s_ready);

    // One-time: 4 Wh columns into registers. lane l holds rows k*128+4l..+3.
    float4 w[4][8];
#pragma unroll
    for (int c = 0; c < 4; c++) {
#pragma unroll
        for (int k = 0; k < 8; k++) {
            int i = k * 128 + lane * 4;
            w[c][k].x = Wh[(size_t)(i + 0) * DDIM + cb + c];
            w[c][k].y = Wh[(size_t)(i + 1) * DDIM + cb + c];
            w[c][k].z = Wh[(size_t)(i + 2) * DDIM + cb + c];
            w[c][k].w = Wh[(size_t)(i + 3) * DDIM + cb + c];
        }
    }

    // Prefetch this segment's first bias (x@Wx + bh), one column per lane 0-3.
    float bias = (lane < 4) ? __ldcg(&g_xwx[(size_t)t_begin * DDIM + cb + lane]) : 0.0f;

    for (int t = t_begin; t < t_end; t++) {
        // Issue next step's bias load now; completes under the wait.
        float bias_next = 0.0f;
        if (t + 1 < t_end && lane < 4)
            bias_next = __ldcg(&g_xwx[(size_t)(t + 1) * DDIM + cb + lane]);

        float a0 = 0.0f, a1 = 0.0f, a2 = 0.0f, a3 = 0.0f;
        if (t > 0) {
            const unsigned tgt = (unsigned)t;
            if (warp == 0) {
                // Poll all 64 per-CTA flags; each lane watches 2 padded
                // sectors (spread across LTS slices). Acquire => strong loads
                // (weak polls livelock on stale L1 -- proven R5/9/10 vs R11).
                unsigned v0f, v1f;
                do {
                    asm volatile("ld.acquire.gpu.global.u32 %0, [%1];"
                                 : "=r"(v0f) : "l"(&g_flag[lane * 8]));
                    asm volatile("ld.acquire.gpu.global.u32 %0, [%1];"
                                 : "=r"(v1f) : "l"(&g_flag[(lane + 32) * 8]));
                } while (__ballot_sync(0xffffffffu,
                                       (v0f >= tgt) && (v1f >= tgt)) != 0xffffffffu);
                // cta-scope release relay: publishes everything warp0 has
                // observed (cumulativity) to warps 1-3.
                if (lane == 0)
                    asm volatile("st.release.cta.shared.u32 [%0], %1;"
                                 :: "r"(s_ready_addr), "r"(tgt));
            } else {
                unsigned r;
                do {
                    asm volatile("ld.acquire.cta.shared.u32 %0, [%1];"
                                 : "=r"(r) : "r"(s_ready_addr));
                } while (r < tgt);
            }

            // Load full h_{t-1}: 8 independent LDG.128.cg per lane (L2 hits).
            const float4* hp = (const float4*)(hidden + (size_t)(t - 1) * DDIM);
            float4 h4[8];
#pragma unroll
            for (int k = 0; k < 8; k++)
                h4[k] = __ldcg(hp + k * 32 + lane);

            // 4 independent dot chains (one per owned column).
#pragma unroll
            for (int k = 0; k < 8; k++) {
                a0 += h4[k].x * w[0][k].x + h4[k].y * w[0][k].y
                    + h4[k].z * w[0][k].z + h4[k].w * w[0][k].w;
                a1 += h4[k].x * w[1][k].x + h4[k].y * w[1][k].y
                    + h4[k].z * w[1][k].z + h4[k].w * w[1][k].w;
                a2 += h4[k].x * w[2][k].x + h4[k].y * w[2][k].y
                    + h4[k].z * w[2][k].z + h4[k].w * w[2][k].w;
                a3 += h4[k].x * w[3][k].x + h4[k].y * w[3][k].y
                    + h4[k].z * w[3][k].z + h4[k].w * w[3][k].w;
            }
            // 4 interleaved butterfly chains.
#pragma unroll
            for (int s = 16; s > 0; s >>= 1) {
                a0 += __shfl_xor_sync(0xffffffffu, a0, s);
                a1 += __shfl_xor_sync(0xffffffffu, a1, s);
                a2 += __shfl_xor_sync(0xffffffffu, a2, s);
                a3 += __shfl_xor_sync(0xffffffffu, a3, s);
            }
        }

        // lanes 0-3 tanh their own column; lane0 packs via shfl, one STG.128.
        float acc = (lane == 0) ? a0 : (lane == 1) ? a1 : (lane == 2) ? a2 : a3;
        float hval = (lane < 4) ? fast_tanh(acc + bias) : 0.0f;
        float h1 = __shfl_sync(0xffffffffu, hval, 1);
        float h2 = __shfl_sync(0xffffffffu, hval, 2);
        float h3 = __shfl_sync(0xffffffffu, hval, 3);

        if (lane == 0) {
            float4 hv; hv.x = hval; hv.y = h1; hv.z = h2; hv.w = h3;
            *(float4*)&hidden[(size_t)t * DDIM + cb] = hv;

            if (t < T_SEQ - 1) {
                // CTA fan-in (acq_rel RMW chain makes all warps' STGs visible
                // to the last arriver), which then releases this CTA's flag.
                unsigned old;
                asm volatile("atom.acq_rel.cta.shared.add.u32 %0, [%1], 1;"
                             : "=r"(old) : "r"(s_arrive_addr));
                if (old == (unsigned)((t - t_begin + 1) * WPB - 1)) {
                    asm volatile("st.release.gpu.global.u32 [%0], %1;"
                                 :: "l"(&g_flag[blockIdx.x * 8]),
                                    "r"((unsigned)(t + 1)));
                }
            }
        }
        bias = bias_next;
    }
}

// ---------------- launch ---------------------------------------------------------
extern "C" void kernel_launch(void* const* d_in, const int* in_sizes, int n_in,
                              void* d_out, int out_size) {
    const float* X  = (const float*)d_in[0];  // [T, D]
    const float* Wx = (const float*)d_in[1];  // [D, D]
    const float* Wh = (const float*)d_in[2];  // [D, D]
    const float* Wy = (const float*)d_in[3];  // [D, D]
    const float* bh = (const float*)d_in[4];  // [D]
    const float* by = (const float*)d_in[5];  // [D]

    float* out    = (float*)d_out;
    float* hidden = out;                         // [T, D]
    float* ys     = out + (size_t)T_SEQ * DDIM;  // [T, D]

    float* xwx_ptr = nullptr;
    unsigned* flag_ptr = nullptr;
    cudaGetSymbolAddress((void**)&xwx_ptr, g_xwx);
    cudaGetSymbolAddress((void**)&flag_ptr, g_flag);

    // Reset per-CTA progress flags (graph-capturable memset node, 2KB).
    cudaMemsetAsync(flag_ptr, 0, 64 * 8 * sizeof(unsigned));

    // 1) XWx = X @ Wx + bh
    {
        dim3 grid(DDIM / 128, T_SEQ / 128);
        sgemm_bias_kernel<<<grid, 256>>>(X, Wx, bh, xwx_ptr, T_SEQ, DDIM, DDIM);
    }

    // 2) Sequential recurrence -> hidden, in 5 segment launches (flags persist
    //    across segments; keeps an rnn segment inside ncu's profile window).
    {
        const int NSEG = 5;
        int t0 = 0;
        for (int s = 0; s < NSEG; s++) {
            int t1 = (int)(((long long)T_SEQ * (s + 1)) / NSEG);
            rnn_recurrence_kernel<<<GBLK, 128>>>(Wh, hidden, t0, t1);
            t0 = t1;
        }
    }

    // 3) Y = H @ Wy + by
    {
        dim3 grid(DDIM / 128, T_SEQ / 128);
        sgemm_bias_kernel<<<grid, 256>>>(hidden, Wy, by, ys, T_SEQ, DDIM, DDIM);
    }
}

// round 14
// speedup vs baseline: 1.1842x; 1.1842x over previous
#include <cuda_runtime.h>
#include <math.h>

// Problem constants (fixed shapes per reference)
#define T_SEQ 16384
#define DDIM  1024

// ---------------- scratch (static device allocations) ----------------------------
__device__ float    g_xwx[T_SEQ * DDIM];   // X@Wx + bh, 64 MB
__device__ unsigned g_cnt[T_SEQ];          // per-step arrival counters (memset/launch)

// ---------------- fp32 SGEMM: C[M,N] = A[M,K] @ B[K,N] + bias[N] ----------------
__global__ __launch_bounds__(256, 2)
void sgemm_bias_kernel(const float* __restrict__ A, const float* __restrict__ B,
                       const float* __restrict__ bias, float* __restrict__ C,
                       int M, int N, int K) {
    __shared__ float As[8][128];
    __shared__ float Bs[8][128];

    const int bx = blockIdx.x;
    const int by = blockIdx.y;
    const int tid = threadIdx.x;

    const int rowA = tid >> 1;
    const int colA = (tid & 1) * 4;
    const int rowB = tid >> 5;
    const int colB = (tid & 31) * 4;

    const int tr = tid / 16;
    const int tc = tid % 16;

    float accum[8][8];
#pragma unroll
    for (int i = 0; i < 8; i++)
#pragma unroll
        for (int j = 0; j < 8; j++) accum[i][j] = 0.0f;

    const float* Aptr = A + (size_t)(by * 128) * K;
    const float* Bptr = B + bx * 128;

    for (int k0 = 0; k0 < K; k0 += 8) {
        float4 a4 = *(const float4*)(Aptr + (size_t)rowA * K + k0 + colA);
        As[colA + 0][rowA] = a4.x;
        As[colA + 1][rowA] = a4.y;
        As[colA + 2][rowA] = a4.z;
        As[colA + 3][rowA] = a4.w;
        float4 b4 = *(const float4*)(Bptr + (size_t)(k0 + rowB) * N + colB);
        *(float4*)&Bs[rowB][colB] = b4;
        __syncthreads();

#pragma unroll
        for (int k = 0; k < 8; k++) {
            float ra[8], rb[8];
            *(float4*)&ra[0] = *(const float4*)&As[k][tr * 8];
            *(float4*)&ra[4] = *(const float4*)&As[k][tr * 8 + 4];
            *(float4*)&rb[0] = *(const float4*)&Bs[k][tc * 8];
            *(float4*)&rb[4] = *(const float4*)&Bs[k][tc * 8 + 4];
#pragma unroll
            for (int i = 0; i < 8; i++)
#pragma unroll
                for (int j = 0; j < 8; j++)
                    accum[i][j] += ra[i] * rb[j];
        }
        __syncthreads();
    }

    const int cRow = by * 128 + tr * 8;
    const int cCol = bx * 128 + tc * 8;
    float bv[8];
#pragma unroll
    for (int j = 0; j < 8; j++) bv[j] = bias[cCol + j];

#pragma unroll
    for (int i = 0; i < 8; i++) {
        float4 v0, v1;
        v0.x = accum[i][0] + bv[0];
        v0.y = accum[i][1] + bv[1];
        v0.z = accum[i][2] + bv[2];
        v0.w = accum[i][3] + bv[3];
        v1.x = accum[i][4] + bv[4];
        v1.y = accum[i][5] + bv[5];
        v1.z = accum[i][6] + bv[6];
        v1.w = accum[i][7] + bv[7];
        *(float4*)&C[(size_t)(cRow + i) * N + cCol]     = v0;
        *(float4*)&C[(size_t)(cRow + i) * N + cCol + 4] = v1;
    }
}

// ---------------- persistent recurrence kernel (segmented, R8 + direct release) --
// 64 CTAs x 128 threads (4 warps). CTA b owns h-columns [16b, 16b+16).
// Warp w owns 4 output columns cb = 16b + 4w .. +3 (Wh cols in registers).
//
// Per step (identical to the R8 champion EXCEPT the producer release):
//  PRODUCE: each warp's lane0 STG.128s its 4 tanh outputs, then IMMEDIATELY
//    issues its own red.release.gpu (+1) on the per-step counter. The release
//    orders that thread's h-store before its increment; cumulative per
//    producer. NO intra-CTA fan-in chain (removes the serialized smem
//    atom.acq_rel arrivals from the critical path). 256 same-word reds/step
//    pipeline at ~0.854 cyc/lane at the LTS.
//  CONSUME: warp0 polls g_cnt[t-1] (all lanes same word -> 1 coalesced strong
//    request per round; acquire => serviced at L2, never stale L1), waits for
//    256, relays via volatile smem word; warps 1-3 LDS-spin. All warps then
//    __ldcg the h row directly.
#define GBLK 64
#define WPB  4
#define ARRIVALS (GBLK * WPB)   // 256 per step

__device__ __forceinline__ float fast_tanh(float x) {
    // tanh(x) = 1 - 2/(e^{2x}+1); MUFU-based, ~1e-7 rel err (tolerance 1e-3).
    float e = __expf(2.0f * x);
    return 1.0f - __fdividef(2.0f, e + 1.0f);
}

__global__ __launch_bounds__(128, 1)
void rnn_recurrence_kernel(const float* __restrict__ Wh, float* __restrict__ hidden,
                           int t_begin, int t_end) {
    __shared__ volatile unsigned s_ready;   // last step whose h is known visible

    const int tid  = threadIdx.x;
    const int lane = tid & 31;
    const int warp = tid >> 5;                      // 0..3
    const int cb   = blockIdx.x * 16 + warp * 4;    // 4 owned output columns

    if (tid == 0) s_ready = (unsigned)t_begin;
    __syncthreads();

    // One-time: 4 Wh columns into registers. lane l holds rows k*128+4l..+3.
    float4 w[4][8];
#pragma unroll
    for (int c = 0; c < 4; c++) {
#pragma unroll
        for (int k = 0; k < 8; k++) {
            int i = k * 128 + lane * 4;
            w[c][k].x = Wh[(size_t)(i + 0) * DDIM + cb + c];
            w[c][k].y = Wh[(size_t)(i + 1) * DDIM + cb + c];
            w[c][k].z = Wh[(size_t)(i + 2) * DDIM + cb + c];
            w[c][k].w = Wh[(size_t)(i + 3) * DDIM + cb + c];
        }
    }

    // Prefetch this segment's first bias (x@Wx + bh), one column per lane 0-3.
    float bias = (lane < 4) ? __ldcg(&g_xwx[(size_t)t_begin * DDIM + cb + lane]) : 0.0f;

    for (int t = t_begin; t < t_end; t++) {
        // Issue next step's bias load now; completes under the wait.
        float bias_next = 0.0f;
        if (t + 1 < t_end && lane < 4)
            bias_next = __ldcg(&g_xwx[(size_t)(t + 1) * DDIM + cb + lane]);

        float a0 = 0.0f, a1 = 0.0f, a2 = 0.0f, a3 = 0.0f;
        if (t > 0) {
            if (warp == 0) {
                // All lanes load the SAME word -> one coalesced request/round.
                const unsigned* cp = &g_cnt[t - 1];
                unsigned v;
                do {
                    asm volatile("ld.acquire.gpu.global.u32 %0, [%1];"
                                 : "=r"(v) : "l"(cp));
                } while (v < (unsigned)ARRIVALS);
                if (lane == 0) s_ready = (unsigned)t;   // publish to CTA
            } else {
                while (s_ready < (unsigned)t) { }       // cheap LDS spin
            }

            // Load full h_{t-1}: 8 independent LDG.128.cg per lane (L2 hits).
            const float4* hp = (const float4*)(hidden + (size_t)(t - 1) * DDIM);
            float4 h4[8];
#pragma unroll
            for (int k = 0; k < 8; k++)
                h4[k] = __ldcg(hp + k * 32 + lane);

            // 4 independent dot chains (one per owned column).
#pragma unroll
            for (int k = 0; k < 8; k++) {
                a0 += h4[k].x * w[0][k].x + h4[k].y * w[0][k].y
                    + h4[k].z * w[0][k].z + h4[k].w * w[0][k].w;
                a1 += h4[k].x * w[1][k].x + h4[k].y * w[1][k].y
                    + h4[k].z * w[1][k].z + h4[k].w * w[1][k].w;
                a2 += h4[k].x * w[2][k].x + h4[k].y * w[2][k].y
                    + h4[k].z * w[2][k].z + h4[k].w * w[2][k].w;
                a3 += h4[k].x * w[3][k].x + h4[k].y * w[3][k].y
                    + h4[k].z * w[3][k].z + h4[k].w * w[3][k].w;
            }
            // 4 interleaved butterfly chains.
#pragma unroll
            for (int s = 16; s > 0; s >>= 1) {
                a0 += __shfl_xor_sync(0xffffffffu, a0, s);
                a1 += __shfl_xor_sync(0xffffffffu, a1, s);
                a2 += __shfl_xor_sync(0xffffffffu, a2, s);
                a3 += __shfl_xor_sync(0xffffffffu, a3, s);
            }
        }

        // lanes 0-3 tanh their own column; lane0 packs via shfl, one STG.128,
        // then its OWN release-red on the per-step counter (no fan-in).
        float acc = (lane == 0) ? a0 : (lane == 1) ? a1 : (lane == 2) ? a2 : a3;
        float hval = (lane < 4) ? fast_tanh(acc + bias) : 0.0f;
        float h1 = __shfl_sync(0xffffffffu, hval, 1);
        float h2 = __shfl_sync(0xffffffffu, hval, 2);
        float h3 = __shfl_sync(0xffffffffu, hval, 3);

        if (lane == 0) {
            float4 hv; hv.x = hval; hv.y = h1; hv.z = h2; hv.w = h3;
            *(float4*)&hidden[(size_t)t * DDIM + cb] = hv;

            if (t < T_SEQ - 1) {
                // Release orders this thread's STG.128 before the increment.
                asm volatile("red.release.gpu.global.add.u32 [%0], 1;"
                             :: "l"(&g_cnt[t]));
            }
        }
        bias = bias_next;
    }
}

// ---------------- launch ---------------------------------------------------------
extern "C" void kernel_launch(void* const* d_in, const int* in_sizes, int n_in,
                              void* d_out, int out_size) {
    const float* X  = (const float*)d_in[0];  // [T, D]
    const float* Wx = (const float*)d_in[1];  // [D, D]
    const float* Wh = (const float*)d_in[2];  // [D, D]
    const float* Wy = (const float*)d_in[3];  // [D, D]
    const float* bh = (const float*)d_in[4];  // [D]
    const float* by = (const float*)d_in[5];  // [D]

    float* out    = (float*)d_out;
    float* hidden = out;                         // [T, D]
    float* ys     = out + (size_t)T_SEQ * DDIM;  // [T, D]

    float* xwx_ptr = nullptr;
    unsigned* cnt_ptr = nullptr;
    cudaGetSymbolAddress((void**)&xwx_ptr, g_xwx);
    cudaGetSymbolAddress((void**)&cnt_ptr, g_cnt);

    // Reset per-step counters (graph-capturable memset node).
    cudaMemsetAsync(cnt_ptr, 0, T_SEQ * sizeof(unsigned));

    // 1) XWx = X @ Wx + bh
    {
        dim3 grid(DDIM / 128, T_SEQ / 128);
        sgemm_bias_kernel<<<grid, 256>>>(X, Wx, bh, xwx_ptr, T_SEQ, DDIM, DDIM);
    }

    // 2) Sequential recurrence -> hidden, in 5 segment launches (counters
    //    persist across segments; keeps an rnn segment in ncu's window).
    {
        const int NSEG = 5;
        int t0 = 0;
        for (int s = 0; s < NSEG; s++) {
            int t1 = (int)(((long long)T_SEQ * (s + 1)) / NSEG);
            rnn_recurrence_kernel<<<GBLK, 128>>>(Wh, hidden, t0, t1);
            t0 = t1;
        }
    }

    // 3) Y = H @ Wy + by
    {
        dim3 grid(DDIM / 128, T_SEQ / 128);
        sgemm_bias_kernel<<<grid, 256>>>(hidden, Wy, by, ys, T_SEQ, DDIM, DDIM);
    }
}

// round 15
// speedup vs baseline: 1.2865x; 1.0864x over previous
#include <cuda_runtime.h>
#include <math.h>

// Problem constants (fixed shapes per reference)
#define T_SEQ 16384
#define DDIM  1024

// ---------------- scratch (static device allocations) ----------------------------
__device__ float    g_xwx[T_SEQ * DDIM];   // X@Wx + bh, 64 MB
__device__ unsigned g_cnt[T_SEQ];          // per-step arrival counters (memset/launch)

// ---------------- fp32 SGEMM: C[M,N] = A[M,K] @ B[K,N] + bias[N] ----------------
__global__ __launch_bounds__(256, 2)
void sgemm_bias_kernel(const float* __restrict__ A, const float* __restrict__ B,
                       const float* __restrict__ bias, float* __restrict__ C,
                       int M, int N, int K) {
    __shared__ float As[8][128];
    __shared__ float Bs[8][128];

    const int bx = blockIdx.x;
    const int by = blockIdx.y;
    const int tid = threadIdx.x;

    const int rowA = tid >> 1;
    const int colA = (tid & 1) * 4;
    const int rowB = tid >> 5;
    const int colB = (tid & 31) * 4;

    const int tr = tid / 16;
    const int tc = tid % 16;

    float accum[8][8];
#pragma unroll
    for (int i = 0; i < 8; i++)
#pragma unroll
        for (int j = 0; j < 8; j++) accum[i][j] = 0.0f;

    const float* Aptr = A + (size_t)(by * 128) * K;
    const float* Bptr = B + bx * 128;

    for (int k0 = 0; k0 < K; k0 += 8) {
        float4 a4 = *(const float4*)(Aptr + (size_t)rowA * K + k0 + colA);
        As[colA + 0][rowA] = a4.x;
        As[colA + 1][rowA] = a4.y;
        As[colA + 2][rowA] = a4.z;
        As[colA + 3][rowA] = a4.w;
        float4 b4 = *(const float4*)(Bptr + (size_t)(k0 + rowB) * N + colB);
        *(float4*)&Bs[rowB][colB] = b4;
        __syncthreads();

#pragma unroll
        for (int k = 0; k < 8; k++) {
            float ra[8], rb[8];
            *(float4*)&ra[0] = *(const float4*)&As[k][tr * 8];
            *(float4*)&ra[4] = *(const float4*)&As[k][tr * 8 + 4];
            *(float4*)&rb[0] = *(const float4*)&Bs[k][tc * 8];
            *(float4*)&rb[4] = *(const float4*)&Bs[k][tc * 8 + 4];
#pragma unroll
            for (int i = 0; i < 8; i++)
#pragma unroll
                for (int j = 0; j < 8; j++)
                    accum[i][j] += ra[i] * rb[j];
        }
        __syncthreads();
    }

    const int cRow = by * 128 + tr * 8;
    const int cCol = bx * 128 + tc * 8;
    float bv[8];
#pragma unroll
    for (int j = 0; j < 8; j++) bv[j] = bias[cCol + j];

#pragma unroll
    for (int i = 0; i < 8; i++) {
        float4 v0, v1;
        v0.x = accum[i][0] + bv[0];
        v0.y = accum[i][1] + bv[1];
        v0.z = accum[i][2] + bv[2];
        v0.w = accum[i][3] + bv[3];
        v1.x = accum[i][4] + bv[4];
        v1.y = accum[i][5] + bv[5];
        v1.z = accum[i][6] + bv[6];
        v1.w = accum[i][7] + bv[7];
        *(float4*)&C[(size_t)(cRow + i) * N + cCol]     = v0;
        *(float4*)&C[(size_t)(cRow + i) * N + cCol + 4] = v1;
    }
}

// ---------------- persistent recurrence kernel (segmented, R8 + direct poll) -----
// 64 CTAs x 128 threads (4 warps). CTA b owns h-columns [16b, 16b+16).
// Warp w owns 4 output columns cb = 16b + 4w .. +3 (Wh cols in registers).
//
// R8 champion with two serial-latency cuts:
//  1. ALL warps poll g_cnt[t-1] directly (all lanes same word -> 1 coalesced
//     strong request per warp per round; 256 warps chip-wide). Removes the
//     smem relay hop from 3/4 of the columns. (R3 proved direct same-word
//     polling is fine even at 512 warps.)
//  2. Producers: lanes 0-3 each store their own column scalar (one coalesced
//     16B transaction), __syncwarp() orders them, then lane0's
//     atom.acq_rel.cta fan-in arrival carries them (A-cumulativity) into the
//     last warp's red.release.gpu on the per-step counter. Removes the 3-shfl
//     pack chain (~80 cyc) from the producer path.
#define GBLK 64
#define WPB  4

__device__ __forceinline__ float fast_tanh(float x) {
    // tanh(x) = 1 - 2/(e^{2x}+1); MUFU-based, ~1e-7 rel err (tolerance 1e-3).
    float e = __expf(2.0f * x);
    return 1.0f - __fdividef(2.0f, e + 1.0f);
}

__global__ __launch_bounds__(128, 1)
void rnn_recurrence_kernel(const float* __restrict__ Wh, float* __restrict__ hidden,
                           int t_begin, int t_end) {
    __shared__ unsigned s_arrive;

    const int tid  = threadIdx.x;
    const int lane = tid & 31;
    const int warp = tid >> 5;                      // 0..3
    const int cb   = blockIdx.x * 16 + warp * 4;    // 4 owned output columns

    if (tid == 0) s_arrive = 0u;
    __syncthreads();
    const unsigned s_arrive_addr = (unsigned)__cvta_generic_to_shared(&s_arrive);

    // One-time: 4 Wh columns into registers. lane l holds rows k*128+4l..+3.
    float4 w[4][8];
#pragma unroll
    for (int c = 0; c < 4; c++) {
#pragma unroll
        for (int k = 0; k < 8; k++) {
            int i = k * 128 + lane * 4;
            w[c][k].x = Wh[(size_t)(i + 0) * DDIM + cb + c];
            w[c][k].y = Wh[(size_t)(i + 1) * DDIM + cb + c];
            w[c][k].z = Wh[(size_t)(i + 2) * DDIM + cb + c];
            w[c][k].w = Wh[(size_t)(i + 3) * DDIM + cb + c];
        }
    }

    // Prefetch this segment's first bias (x@Wx + bh), one column per lane 0-3.
    float bias = (lane < 4) ? __ldcg(&g_xwx[(size_t)t_begin * DDIM + cb + lane]) : 0.0f;

    for (int t = t_begin; t < t_end; t++) {
        // Issue next step's bias load now; completes under the wait.
        float bias_next = 0.0f;
        if (t + 1 < t_end && lane < 4)
            bias_next = __ldcg(&g_xwx[(size_t)(t + 1) * DDIM + cb + lane]);

        float a0 = 0.0f, a1 = 0.0f, a2 = 0.0f, a3 = 0.0f;
        if (t > 0) {
            // Every warp polls directly: all lanes load the SAME word -> one
            // coalesced strong request per warp per round. Acquire semantics
            // (serviced at L2) synchronize-with the producers' releases.
            {
                const unsigned* cp = &g_cnt[t - 1];
                unsigned v;
                do {
                    asm volatile("ld.acquire.gpu.global.u32 %0, [%1];"
                                 : "=r"(v) : "l"(cp));
                } while (v < (unsigned)GBLK);
            }

            // Load full h_{t-1}: 8 independent LDG.128.cg per lane (L2 hits).
            const float4* hp = (const float4*)(hidden + (size_t)(t - 1) * DDIM);
            float4 h4[8];
#pragma unroll
            for (int k = 0; k < 8; k++)
                h4[k] = __ldcg(hp + k * 32 + lane);

            // 4 independent dot chains (one per owned column).
#pragma unroll
            for (int k = 0; k < 8; k++) {
                a0 += h4[k].x * w[0][k].x + h4[k].y * w[0][k].y
                    + h4[k].z * w[0][k].z + h4[k].w * w[0][k].w;
                a1 += h4[k].x * w[1][k].x + h4[k].y * w[1][k].y
                    + h4[k].z * w[1][k].z + h4[k].w * w[1][k].w;
                a2 += h4[k].x * w[2][k].x + h4[k].y * w[2][k].y
                    + h4[k].z * w[2][k].z + h4[k].w * w[2][k].w;
                a3 += h4[k].x * w[3][k].x + h4[k].y * w[3][k].y
                    + h4[k].z * w[3][k].z + h4[k].w * w[3][k].w;
            }
            // 4 interleaved butterfly chains.
#pragma unroll
            for (int s = 16; s > 0; s >>= 1) {
                a0 += __shfl_xor_sync(0xffffffffu, a0, s);
                a1 += __shfl_xor_sync(0xffffffffu, a1, s);
                a2 += __shfl_xor_sync(0xffffffffu, a2, s);
                a3 += __shfl_xor_sync(0xffffffffu, a3, s);
            }
        }

        // lanes 0-3 tanh + store their own column (one coalesced 16B txn).
        float acc = (lane == 0) ? a0 : (lane == 1) ? a1 : (lane == 2) ? a2 : a3;
        if (lane < 4) {
            float hval = fast_tanh(acc + bias);
            asm volatile("st.global.cg.f32 [%0], %1;"
                         :: "l"(&hidden[(size_t)t * DDIM + cb + lane]),
                            "f"(hval) : "memory");
        }
        __syncwarp();   // orders lanes' stores before lane0's fan-in arrival

        if (lane == 0 && t < T_SEQ - 1) {
            // CTA fan-in (acq_rel RMW chain carries all warps' stores to the
            // last arriver), which then releases this CTA's step increment.
            unsigned old;
            asm volatile("atom.acq_rel.cta.shared.add.u32 %0, [%1], 1;"
                         : "=r"(old) : "r"(s_arrive_addr));
            if (old == (unsigned)((t - t_begin + 1) * WPB - 1)) {
                asm volatile("red.release.gpu.global.add.u32 [%0], 1;"
                             :: "l"(&g_cnt[t]));
            }
        }
        bias = bias_next;
    }
}

// ---------------- launch ---------------------------------------------------------
extern "C" void kernel_launch(void* const* d_in, const int* in_sizes, int n_in,
                              void* d_out, int out_size) {
    const float* X  = (const float*)d_in[0];  // [T, D]
    const float* Wx = (const float*)d_in[1];  // [D, D]
    const float* Wh = (const float*)d_in[2];  // [D, D]
    const float* Wy = (const float*)d_in[3];  // [D, D]
    const float* bh = (const float*)d_in[4];  // [D]
    const float* by = (const float*)d_in[5];  // [D]

    float* out    = (float*)d_out;
    float* hidden = out;                         // [T, D]
    float* ys     = out + (size_t)T_SEQ * DDIM;  // [T, D]

    float* xwx_ptr = nullptr;
    unsigned* cnt_ptr = nullptr;
    cudaGetSymbolAddress((void**)&xwx_ptr, g_xwx);
    cudaGetSymbolAddress((void**)&cnt_ptr, g_cnt);

    // Reset per-step counters (graph-capturable memset node).
    cudaMemsetAsync(cnt_ptr, 0, T_SEQ * sizeof(unsigned));

    // 1) XWx = X @ Wx + bh
    {
        dim3 grid(DDIM / 128, T_SEQ / 128);
        sgemm_bias_kernel<<<grid, 256>>>(X, Wx, bh, xwx_ptr, T_SEQ, DDIM, DDIM);
    }

    // 2) Sequential recurrence -> hidden, in 4 segment launches of 4096 steps
    //    (counters persist across segments; 4096 = 32*128 rows preps per-
    //    segment y-GEMM overlap; keeps an rnn segment in ncu's window).
    {
        const int NSEG = 4;
        int t0 = 0;
        for (int s = 0; s < NSEG; s++) {
            int t1 = (T_SEQ / NSEG) * (s + 1);
            rnn_recurrence_kernel<<<GBLK, 128>>>(Wh, hidden, t0, t1);
            t0 = t1;
        }
    }

    // 3) Y = H @ Wy + by
    {
        dim3 grid(DDIM / 128, T_SEQ / 128);
        sgemm_bias_kernel<<<grid, 256>>>(hidden, Wy, by, ys, T_SEQ, DDIM, DDIM);
    }
}